// round 5
// baseline (speedup 1.0000x reference)
#include <cuda_runtime.h>
#include <cstdint>

// QuantumLikeLayer: out[b,:] = CZ_diag * (H^{⊗11} @ in[b,:]), N=2048, FWHT.
// Persistent warps + cp.async.bulk (TMA-path) input prefetch:
//   bulk G->S into per-warp in-buffer (0 L1tex wavefronts, mbarrier completion)
//   LDS.128 layout-A read (fused i0) -> P1 (i1,i7..i10 in regs)
//   issue next row's bulk copy (overlaps rest of the row)
//   exch1 (8B/16B, XOR swizzle) -> P2 (i2..i6) -> CZ sign+scale
//   exch2 -> coalesced STG.128

#define NN 2048
#define NWARP 7
#define THREADS 224
typedef unsigned long long u64;

__device__ __forceinline__ u64 pk(float x, float y) {
    u64 d; asm("mov.b64 %0,{%1,%2};" : "=l"(d) : "f"(x), "f"(y)); return d;
}
__device__ __forceinline__ void upk(u64 v, float& x, float& y) {
    asm("mov.b64 {%0,%1},%2;" : "=f"(x), "=f"(y) : "l"(v));
}
__device__ __forceinline__ u64 padd(u64 a, u64 b) {
    u64 d; asm("add.rn.f32x2 %0,%1,%2;" : "=l"(d) : "l"(a), "l"(b)); return d;
}
__device__ __forceinline__ u64 pfma(u64 a, u64 b, u64 c) {
    u64 d; asm("fma.rn.f32x2 %0,%1,%2,%3;" : "=l"(d) : "l"(a), "l"(b), "l"(c)); return d;
}
__device__ __forceinline__ u64 pmul(u64 a, u64 b) {
    u64 d; asm("mul.rn.f32x2 %0,%1,%2;" : "=l"(d) : "l"(a), "l"(b)); return d;
}

template <int M>
__device__ __forceinline__ void bfly(u64 v[32], u64 NEG1) {
#pragma unroll
    for (int r = 0; r < 32; r++) {
        if (!(r & M)) {
            u64 a = v[r], b = v[r | M];
            v[r]     = padd(a, b);
            v[r | M] = pfma(b, NEG1, a);   // a - b
        }
    }
}

__device__ __forceinline__ void mbar_wait(uint32_t mbar, int ph) {
    asm volatile(
        "{\n\t.reg .pred P;\n"
        "W%=:\n\t"
        "mbarrier.try_wait.parity.acquire.cta.shared::cta.b64 P, [%0], %1, 0x989680;\n\t"
        "@P bra D%=;\n\t"
        "bra W%=;\n"
        "D%=:\n\t}"
        :: "r"(mbar), "r"(ph) : "memory");
}

__global__ void __launch_bounds__(THREADS, 2)
fwht_cz_kernel(const float4* __restrict__ in, float4* __restrict__ out, int rows) {
    extern __shared__ u64 dyn[];          // per warp: [0..1023] in-buf, [1024..2047] exch
    __shared__ u64 mbars[NWARP];

    const int lane = threadIdx.x & 31;
    const int wid  = threadIdx.x >> 5;

    u64* inbuf = dyn + wid * 2048;
    u64* exbuf = inbuf + 1024;
    const uint32_t inb_s = (uint32_t)__cvta_generic_to_shared(inbuf);
    const uint32_t mbar  = (uint32_t)__cvta_generic_to_shared(&mbars[wid]);

    if (lane == 0) {
        asm volatile("mbarrier.init.shared.b64 [%0], %1;" :: "r"(mbar), "r"(1) : "memory");
        asm volatile("fence.proxy.async.shared::cta;" ::: "memory");
    }
    __syncwarp();

    const int gw     = blockIdx.x * NWARP + wid;
    const int stride = gridDim.x * NWARP;

    // prefetch first row
    if (lane == 0 && gw < rows) {
        asm volatile("mbarrier.arrive.expect_tx.shared::cta.b64 _, [%0], %1;"
                     :: "r"(mbar), "r"(8192) : "memory");
        const float4* g = in + (size_t)gw * (NN / 4);
        asm volatile("cp.async.bulk.shared::cluster.global.mbarrier::complete_tx::bytes "
                     "[%0], [%1], %2, [%3];"
                     :: "r"(inb_s), "l"(g), "r"(8192), "r"(mbar) : "memory");
    }

    const u64 NEG1 = pk(-1.0f, -1.0f);
    const int colw = lane >> 1;
    const int h    = lane & 1;
    const int m15  = lane & 15;
    const float S  = 0.022097086912079608f;   // 2^{-5.5}
    const float scf = ((lane & 24) == 24) ? -S : S;
    const u64 sc2 = pk(scf, scf);

    int ph = 0;
    for (int row = gw; row < rows; row += stride) {
        mbar_wait(mbar, ph);
        ph ^= 1;

        // ---- LDS.128 layout A (f = lane + 32j; comps i0,i1; j = i7..i10), fuse i0 ----
        const float4* inf4 = (const float4*)inbuf;
        u64 v[32];
#pragma unroll
        for (int j = 0; j < 16; j++) {
            float4 q = inf4[lane + 32 * j];
            v[2 * j]     = pk(q.x + q.y, q.x - q.y);   // i1 = 0
            v[2 * j + 1] = pk(q.z + q.w, q.z - q.w);   // i1 = 1
        }

        // ---- P1: i1 (bit0), i7..i10 (bits 1..4) ----
        bfly<1>(v, NEG1); bfly<2>(v, NEG1); bfly<4>(v, NEG1);
        bfly<8>(v, NEG1); bfly<16>(v, NEG1);

        __syncwarp();   // all lanes consumed in-buf (P1 done) -> safe to refill
        {
            int nrow = row + stride;
            if (lane == 0 && nrow < rows) {
                asm volatile("mbarrier.arrive.expect_tx.shared::cta.b64 _, [%0], %1;"
                             :: "r"(mbar), "r"(8192) : "memory");
                const float4* g = in + (size_t)nrow * (NN / 4);
                asm volatile("cp.async.bulk.shared::cluster.global.mbarrier::complete_tx::bytes "
                             "[%0], [%1], %2, [%3];"
                             :: "r"(inb_s), "l"(g), "r"(8192), "r"(mbar) : "memory");
            }
        }

        // ---- exch1 write: STS.64 swizzled (r = i1+2*i7+4*i8+8*i9+16*i10) ----
#pragma unroll
        for (int r = 0; r < 32; r++)
            exbuf[32 * r + 2 * (colw ^ (r & 15)) + h] = v[r];
        __syncwarp();

        // ---- exch1 read: LDS.128, thread owns region r = lane ----
        const float4* exf4 = (const float4*)exbuf;
#pragma unroll
        for (int k = 0; k < 16; k++) {
            float4 q = exf4[16 * lane + (k ^ m15)];
            v[2 * k]     = pk(q.x, q.y);   // i2 = 0
            v[2 * k + 1] = pk(q.z, q.w);   // i2 = 1
        }

        // ---- P2: i2 (bit0), i3..i6 (bits 1..4) ----
        bfly<1>(v, NEG1); bfly<2>(v, NEG1); bfly<4>(v, NEG1);
        bfly<8>(v, NEG1); bfly<16>(v, NEG1);

        // ---- CZ sign + 2^{-5.5}: i9,i10 = lane bits 3,4 -> thread-uniform ----
#pragma unroll
        for (int r = 0; r < 32; r++) v[r] = pmul(v[r], sc2);
        __syncwarp();   // exch1 reads complete before exch2 writes

        // ---- exch2 write: STS.128 (same slots as exch1 read) ----
        float4* exw = (float4*)exbuf;
#pragma unroll
        for (int k = 0; k < 16; k++) {
            float a, b, c, d;
            upk(v[2 * k], a, b); upk(v[2 * k + 1], c, d);
            exw[16 * lane + (k ^ m15)] = make_float4(a, b, c, d);
        }
        __syncwarp();

        // ---- exch2 read: LDS.64 + coalesced STG.128 ----
        float4* __restrict__ op = out + (size_t)row * (NN / 4);
#pragma unroll
        for (int j = 0; j < 16; j++) {
            int r0 = 2 * j, r1 = 2 * j + 1;
            u64 u0 = exbuf[32 * r0 + 2 * (colw ^ (r0 & 15)) + h];   // i1 = 0
            u64 u1 = exbuf[32 * r1 + 2 * (colw ^ (r1 & 15)) + h];   // i1 = 1
            float a, b, c, d;
            upk(u0, a, b); upk(u1, c, d);
            op[lane + 32 * j] = make_float4(a, b, c, d);
        }
        // next iteration's exch1-write is ordered behind the post-P1 __syncwarp
    }
}

extern "C" void kernel_launch(void* const* d_in, const int* in_sizes, int n_in,
                              void* d_out, int out_size) {
    const float4* in = (const float4*)d_in[0];
    float4* out = (float4*)d_out;
    const int rows = in_sizes[0] / NN;            // 16384
    const int smem = NWARP * 2048 * sizeof(u64);  // 114688 B
    cudaFuncSetAttribute(fwht_cz_kernel,
                         cudaFuncAttributeMaxDynamicSharedMemorySize, smem);
    fwht_cz_kernel<<<296, THREADS, smem>>>(in, out, rows);
}

// round 6
// speedup vs baseline: 1.0108x; 1.0108x over previous
#include <cuda_runtime.h>
#include <cstdint>

// QuantumLikeLayer: out[b,:] = CZ_diag * (H^{⊗11} @ in[b,:]), N=2048, FWHT.
// Persistent warps, double-buffered cp.async.bulk input prefetch with a full
// row of lookahead; each row's input buffer doubles as its exchange scratch.
//   buf[cur]: TMA G->S (prefetched last iter) -> LDS.128 load (fuse i0)
//   P1 (i1,i7..i10 regs) -> exch1 (8B/16B XOR swizzle) -> P2 (i2..i6)
//   CZ sign + 2^-5.5 -> exch2 -> coalesced STG.128
// Meanwhile buf[cur^1] receives row k+1 via TMA.

#define NN 2048
#define NWARP 4
#define THREADS 128
typedef unsigned long long u64;

__device__ __forceinline__ u64 pk(float x, float y) {
    u64 d; asm("mov.b64 %0,{%1,%2};" : "=l"(d) : "f"(x), "f"(y)); return d;
}
__device__ __forceinline__ void upk(u64 v, float& x, float& y) {
    asm("mov.b64 {%0,%1},%2;" : "=f"(x), "=f"(y) : "l"(v));
}
__device__ __forceinline__ u64 padd(u64 a, u64 b) {
    u64 d; asm("add.rn.f32x2 %0,%1,%2;" : "=l"(d) : "l"(a), "l"(b)); return d;
}
__device__ __forceinline__ u64 pfma(u64 a, u64 b, u64 c) {
    u64 d; asm("fma.rn.f32x2 %0,%1,%2,%3;" : "=l"(d) : "l"(a), "l"(b), "l"(c)); return d;
}
__device__ __forceinline__ u64 pmul(u64 a, u64 b) {
    u64 d; asm("mul.rn.f32x2 %0,%1,%2;" : "=l"(d) : "l"(a), "l"(b)); return d;
}

template <int M>
__device__ __forceinline__ void bfly(u64 v[32], u64 NEG1) {
#pragma unroll
    for (int r = 0; r < 32; r++) {
        if (!(r & M)) {
            u64 a = v[r], b = v[r | M];
            v[r]     = padd(a, b);
            v[r | M] = pfma(b, NEG1, a);   // a - b
        }
    }
}

__device__ __forceinline__ void mbar_wait(uint32_t mbar, int ph) {
    asm volatile(
        "{\n\t.reg .pred P;\n"
        "W%=:\n\t"
        "mbarrier.try_wait.parity.acquire.cta.shared::cta.b64 P, [%0], %1, 0x989680;\n\t"
        "@P bra D%=;\n\t"
        "bra W%=;\n"
        "D%=:\n\t}"
        :: "r"(mbar), "r"(ph) : "memory");
}

__device__ __forceinline__ void prefetch_row(uint32_t dst_s, const float4* g,
                                             uint32_t mbar) {
    asm volatile("mbarrier.arrive.expect_tx.shared::cta.b64 _, [%0], %1;"
                 :: "r"(mbar), "r"(8192) : "memory");
    asm volatile("cp.async.bulk.shared::cluster.global.mbarrier::complete_tx::bytes "
                 "[%0], [%1], %2, [%3];"
                 :: "r"(dst_s), "l"(g), "r"(8192), "r"(mbar) : "memory");
}

__global__ void __launch_bounds__(THREADS, 3)
fwht_cz_kernel(const float4* __restrict__ in, float4* __restrict__ out,
               int rows, int stride_rows) {
    extern __shared__ u64 dyn[];          // per warp: 2 x 1024 u64 (8KB each)
    __shared__ u64 mbars[NWARP][2];

    const int lane = threadIdx.x & 31;
    const int wid  = threadIdx.x >> 5;

    u64* b0 = dyn + wid * 2048;
    u64* b1 = b0 + 1024;
    const uint32_t bs0 = (uint32_t)__cvta_generic_to_shared(b0);
    const uint32_t bs1 = (uint32_t)__cvta_generic_to_shared(b1);
    const uint32_t mb0 = (uint32_t)__cvta_generic_to_shared(&mbars[wid][0]);
    const uint32_t mb1 = (uint32_t)__cvta_generic_to_shared(&mbars[wid][1]);

    if (lane == 0) {
        asm volatile("mbarrier.init.shared.b64 [%0], %1;" :: "r"(mb0), "r"(1) : "memory");
        asm volatile("mbarrier.init.shared.b64 [%0], %1;" :: "r"(mb1), "r"(1) : "memory");
        asm volatile("fence.proxy.async.shared::cta;" ::: "memory");
    }
    __syncwarp();

    const int gw = blockIdx.x * NWARP + wid;

    if (lane == 0 && gw < rows)
        prefetch_row(bs0, in + (size_t)gw * (NN / 4), mb0);

    const u64 NEG1 = pk(-1.0f, -1.0f);
    const int colw = lane >> 1;
    const int h    = lane & 1;
    const int m15  = lane & 15;
    const float S  = 0.022097086912079608f;   // 2^{-5.5}
    const float scf = ((lane & 24) == 24) ? -S : S;
    const u64 sc2 = pk(scf, scf);

    int ph0 = 0, ph1 = 0;
    int k = 0;
    for (int row = gw; row < rows; row += stride_rows, k++) {
        const int  cur  = k & 1;
        u64*       bufc = cur ? b1 : b0;

        // all lanes done with buf[cur^1] (previous row) -> prefetch row k+1 into it
        __syncwarp();
        {
            int nrow = row + stride_rows;
            if (lane == 0 && nrow < rows)
                prefetch_row(cur ? bs0 : bs1, in + (size_t)nrow * (NN / 4),
                             cur ? mb0 : mb1);
        }

        // wait for row k's data
        if (cur == 0) { mbar_wait(mb0, ph0); ph0 ^= 1; }
        else          { mbar_wait(mb1, ph1); ph1 ^= 1; }

        // ---- load from smem (f = lane + 32j; comps i0,i1; j = i7..i10), fuse i0 ----
        const float4* inf4 = (const float4*)bufc;
        u64 v[32];
#pragma unroll
        for (int j = 0; j < 16; j++) {
            float4 q = inf4[lane + 32 * j];
            v[2 * j]     = pk(q.x + q.y, q.x - q.y);   // i1 = 0
            v[2 * j + 1] = pk(q.z + q.w, q.z - q.w);   // i1 = 1
        }

        // ---- P1: i1 (bit0), i7..i10 (bits 1..4) ----
        bfly<1>(v, NEG1); bfly<2>(v, NEG1); bfly<4>(v, NEG1);
        bfly<8>(v, NEG1); bfly<16>(v, NEG1);
        __syncwarp();   // all lanes consumed input -> buffer reusable as scratch

        // ---- exch1 write: STS.64 swizzled (r = i1+2*i7+4*i8+8*i9+16*i10) ----
#pragma unroll
        for (int r = 0; r < 32; r++)
            bufc[32 * r + 2 * (colw ^ (r & 15)) + h] = v[r];
        __syncwarp();

        // ---- exch1 read: LDS.128, thread owns region r = lane ----
        const float4* exf4 = (const float4*)bufc;
#pragma unroll
        for (int kk = 0; kk < 16; kk++) {
            float4 q = exf4[16 * lane + (kk ^ m15)];
            v[2 * kk]     = pk(q.x, q.y);   // i2 = 0
            v[2 * kk + 1] = pk(q.z, q.w);   // i2 = 1
        }

        // ---- P2: i2 (bit0), i3..i6 (bits 1..4) ----
        bfly<1>(v, NEG1); bfly<2>(v, NEG1); bfly<4>(v, NEG1);
        bfly<8>(v, NEG1); bfly<16>(v, NEG1);

        // ---- CZ sign + 2^{-5.5}: i9,i10 = lane bits 3,4 -> thread-uniform ----
#pragma unroll
        for (int r = 0; r < 32; r++) v[r] = pmul(v[r], sc2);
        __syncwarp();   // exch1 reads complete before exch2 writes

        // ---- exch2 write: STS.128 (same slots as exch1 read) ----
        float4* exw = (float4*)bufc;
#pragma unroll
        for (int kk = 0; kk < 16; kk++) {
            float a, b, c, d;
            upk(v[2 * kk], a, b); upk(v[2 * kk + 1], c, d);
            exw[16 * lane + (kk ^ m15)] = make_float4(a, b, c, d);
        }
        __syncwarp();

        // ---- exch2 read: LDS.64 + coalesced STG.128 ----
        float4* __restrict__ op = out + (size_t)row * (NN / 4);
#pragma unroll
        for (int j = 0; j < 16; j++) {
            int r0 = 2 * j, r1 = 2 * j + 1;
            u64 u0 = bufc[32 * r0 + 2 * (colw ^ (r0 & 15)) + h];   // i1 = 0
            u64 u1 = bufc[32 * r1 + 2 * (colw ^ (r1 & 15)) + h];   // i1 = 1
            float a, b, c, d;
            upk(u0, a, b); upk(u1, c, d);
            op[lane + 32 * j] = make_float4(a, b, c, d);
        }
    }
}

extern "C" void kernel_launch(void* const* d_in, const int* in_sizes, int n_in,
                              void* d_out, int out_size) {
    const float4* in = (const float4*)d_in[0];
    float4* out = (float4*)d_out;
    const int rows = in_sizes[0] / NN;                 // 16384
    const int grid = 444;                              // 148 SMs x 3 CTAs
    const int stride_rows = grid * NWARP;              // 1776
    const int smem = NWARP * 2048 * sizeof(u64);       // 65536 B
    cudaFuncSetAttribute(fwht_cz_kernel,
                         cudaFuncAttributeMaxDynamicSharedMemorySize, smem);
    fwht_cz_kernel<<<grid, THREADS, smem>>>(in, out, rows, stride_rows);
}

// round 7
// speedup vs baseline: 1.2404x; 1.2271x over previous
#include <cuda_runtime.h>
#include <cstdint>

// QuantumLikeLayer: out[b,:] = CZ_diag * (H^{⊗11} @ in[b,:]), N=2048, FWHT.
// R4 structure (one warp/row, 64 elems/thread, zero shuffles, two smem
// exchanges) + bulk L2 prefetch one wave ahead + streaming cache hints.
//   load  (coalesced LDG.128, __ldcs): regs carry i0 (pack), i1, i7..i10
//   P1: 6 reg stages -> exch1 (8B/16B XOR swizzle) -> P2: i2..i6
//   CZ sign + 2^-5.5 thread-uniform -> exch2 -> coalesced STG.128 (__stcs)

#define NN 2048
typedef unsigned long long u64;

// prefetch distance in rows = one full wave (148 SMs x 4 CTAs x 4 rows)
#define PF_ROWS 2368

__device__ __forceinline__ u64 pk(float x, float y) {
    u64 d; asm("mov.b64 %0,{%1,%2};" : "=l"(d) : "f"(x), "f"(y)); return d;
}
__device__ __forceinline__ void upk(u64 v, float& x, float& y) {
    asm("mov.b64 {%0,%1},%2;" : "=f"(x), "=f"(y) : "l"(v));
}
__device__ __forceinline__ u64 padd(u64 a, u64 b) {
    u64 d; asm("add.rn.f32x2 %0,%1,%2;" : "=l"(d) : "l"(a), "l"(b)); return d;
}
__device__ __forceinline__ u64 pfma(u64 a, u64 b, u64 c) {
    u64 d; asm("fma.rn.f32x2 %0,%1,%2,%3;" : "=l"(d) : "l"(a), "l"(b), "l"(c)); return d;
}
__device__ __forceinline__ u64 pmul(u64 a, u64 b) {
    u64 d; asm("mul.rn.f32x2 %0,%1,%2;" : "=l"(d) : "l"(a), "l"(b)); return d;
}

template <int M>
__device__ __forceinline__ void bfly(u64 v[32], u64 NEG1) {
#pragma unroll
    for (int r = 0; r < 32; r++) {
        if (!(r & M)) {
            u64 a = v[r], b = v[r | M];
            v[r]     = padd(a, b);
            v[r | M] = pfma(b, NEG1, a);   // a - b
        }
    }
}

__global__ void __launch_bounds__(128, 4)
fwht_cz_kernel(const float4* __restrict__ in, float4* __restrict__ out, int rows) {
    // smem per warp (8KB, 1024 u64): unit (r, col, h): idx = 32r + 2*(col ^ (r&15)) + h
    //   r = i1 + 2*i7 + 4*i8 + 8*i9 + 16*i10 ; col = i3..i6 ; h = i2 ; u64 = i0 pair
    __shared__ u64 sm[4][1024];

    const int lane = threadIdx.x & 31;
    const int wid  = threadIdx.x >> 5;
    const int row  = (blockIdx.x << 2) + wid;

    const float4* __restrict__ ip = in  + (size_t)row * (NN / 4);
    float4* __restrict__       op = out + (size_t)row * (NN / 4);
    u64* sw = sm[wid];

    // ---- bulk L2 prefetch for the row this warp slot owns one wave later ----
    if (lane == 0) {
        int pr = row + PF_ROWS;
        if (pr < rows) {
            const float4* g = in + (size_t)pr * (NN / 4);
            asm volatile("cp.async.bulk.prefetch.L2.global [%0], %1;"
                         :: "l"(g), "r"(8192) : "memory");
        }
    }

    const u64 NEG1 = pk(-1.0f, -1.0f);
    u64 v[32];

    // ---- load (f = lane + 32j; lane = i2..i6, j = i7..i10, comps = i0,i1) ----
    // evict-first read; fuse i0 stage; pack slot = i0; reg r = i1 + 2*j
#pragma unroll
    for (int j = 0; j < 16; j++) {
        float4 q = __ldcs(&ip[lane + 32 * j]);
        v[2 * j]     = pk(q.x + q.y, q.x - q.y);   // i1 = 0
        v[2 * j + 1] = pk(q.z + q.w, q.z - q.w);   // i1 = 1
    }

    // ---- P1: i1 (bit0), i7..i10 (bits 1..4) ----
    bfly<1>(v, NEG1); bfly<2>(v, NEG1); bfly<4>(v, NEG1);
    bfly<8>(v, NEG1); bfly<16>(v, NEG1);

    // ---- exch1 write: STS.64 swizzled ----
    const int colw = lane >> 1;
    const int h    = lane & 1;
#pragma unroll
    for (int r = 0; r < 32; r++)
        sw[32 * r + 2 * (colw ^ (r & 15)) + h] = v[r];
    __syncwarp();

    // ---- exch1 read: LDS.128, thread owns region r = lane ----
    const float4* swf4 = (const float4*)sw;
    const int m15 = lane & 15;
#pragma unroll
    for (int k = 0; k < 16; k++) {
        float4 q = swf4[16 * lane + (k ^ m15)];
        v[2 * k]     = pk(q.x, q.y);   // i2 = 0
        v[2 * k + 1] = pk(q.z, q.w);   // i2 = 1
    }

    // ---- P2: i2 (bit0), i3..i6 (bits 1..4) ----
    bfly<1>(v, NEG1); bfly<2>(v, NEG1); bfly<4>(v, NEG1);
    bfly<8>(v, NEG1); bfly<16>(v, NEG1);

    // ---- CZ sign + 2^{-5.5}: i9,i10 = lane bits 3,4 -> thread-uniform ----
    {
        const float S  = 0.022097086912079608f;   // 2^{-5.5}
        float sc = ((lane & 24) == 24) ? -S : S;
        u64 sc2 = pk(sc, sc);
#pragma unroll
        for (int r = 0; r < 32; r++) v[r] = pmul(v[r], sc2);
    }
    __syncwarp();   // exch1 reads complete before exch2 writes

    // ---- exch2 write: STS.128 (same slots as exch1 read) ----
    float4* swf4w = (float4*)sw;
#pragma unroll
    for (int k = 0; k < 16; k++) {
        float a, b, c, d;
        upk(v[2 * k], a, b); upk(v[2 * k + 1], c, d);
        swf4w[16 * lane + (k ^ m15)] = make_float4(a, b, c, d);
    }
    __syncwarp();

    // ---- exch2 read: LDS.64 + coalesced streaming STG.128 ----
#pragma unroll
    for (int j = 0; j < 16; j++) {
        int r0 = 2 * j, r1 = 2 * j + 1;
        u64 u0 = sw[32 * r0 + 2 * (colw ^ (r0 & 15)) + h];   // i1 = 0
        u64 u1 = sw[32 * r1 + 2 * (colw ^ (r1 & 15)) + h];   // i1 = 1
        float a, b, c, d;
        upk(u0, a, b); upk(u1, c, d);
        __stcs(&op[lane + 32 * j], make_float4(a, b, c, d));
    }
}

extern "C" void kernel_launch(void* const* d_in, const int* in_sizes, int n_in,
                              void* d_out, int out_size) {
    const float4* in = (const float4*)d_in[0];
    float4* out = (float4*)d_out;
    const int rows = in_sizes[0] / NN;    // 16384
    fwht_cz_kernel<<<rows / 4, 128>>>(in, out, rows);
}